// round 1
// baseline (speedup 1.0000x reference)
#include <cuda_runtime.h>
#include <cuda_bf16.h>
#include <cstddef>

// Problem constants
#define BB 4
#define LL 2048
#define DM 512
#define DI 1024            // D_INNER
#define DS 16              // D_STATE
#define DTR 32             // DT_RANK
#define ML (BB*LL)         // 8192 rows

// ---------------- scratch (no allocations allowed) ----------------
__device__ float g_xz  [(size_t)ML * 2 * DI];  // [8192, 2048]  in_proj output (x | z)
__device__ float g_xc  [(size_t)ML * DI];      // [8192, 1024]  conv+silu output (u)
__device__ float g_xdbl[(size_t)ML * 64];      // [8192, 64]    x_proj output (dt_lr | B | C)
__device__ float g_dt  [(size_t)ML * DI];      // [8192, 1024]  softplus dt
__device__ float g_ys  [(size_t)ML * DI];      // [8192, 1024]  scan output -> gated y

// ---------------- helpers ----------------
__device__ __forceinline__ float fexp(float x) {
    // exp(x) via 2^y, FMA-pipe only (avoids MUFU throughput wall in the scan)
    float y = x * 1.4426950408889634f;
    y = fmaxf(y, -126.0f);
    float r = rintf(y);
    float f = y - r;
    // 2^f on [-0.5, 0.5], degree-5 Taylor of exp(f*ln2), rel err ~2e-6
    float p = 0.0013333558f;
    p = fmaf(p, f, 0.0096181298f);
    p = fmaf(p, f, 0.0555041087f);
    p = fmaf(p, f, 0.2402265070f);
    p = fmaf(p, f, 0.6931471806f);
    p = fmaf(p, f, 1.0f);
    int e = (int)r;
    return __int_as_float(__float_as_int(p) + (e << 23));
}

__device__ __forceinline__ float softplusf(float x) {
    return (x > 20.f) ? x : log1pf(__expf(x));
}

__device__ __forceinline__ float siluf(float x) {
    return x / (1.f + __expf(-x));
}

// ---------------- SGEMM: C[m,n] = sum_k A[m,k] * W[n,k]  (+bias, +softplus) ----
// BM=128, BN=64, BK=16, 256 threads, 8x4 register tile per thread.
template <int ACT>
__global__ void sgemm_kernel(const float* __restrict__ A, const float* __restrict__ W,
                             const float* __restrict__ bias, float* __restrict__ C,
                             int K, int lda, int ldw, int ldc) {
    __shared__ float As[16 * 132];
    __shared__ float Bs[16 * 68];
    const int tid = threadIdx.x;
    const int tx = tid & 15;          // 0..15 -> 4 cols each
    const int ty = tid >> 4;          // 0..15 -> 8 rows each
    const int bm = blockIdx.y * 128;
    const int bn = blockIdx.x * 64;

    const float* Ab = A + (size_t)bm * lda;
    const float* Wb = W + (size_t)bn * ldw;

    float acc[8][4];
#pragma unroll
    for (int i = 0; i < 8; i++)
#pragma unroll
        for (int j = 0; j < 4; j++) acc[i][j] = 0.f;

    for (int k0 = 0; k0 < K; k0 += 16) {
        // A tile: 128x16, 2 float4 per thread, store transposed [k][m]
#pragma unroll
        for (int i = 0; i < 2; i++) {
            int qid = tid + i * 256;
            int r = qid >> 2, q = qid & 3;
            float4 v = *(const float4*)(Ab + (size_t)r * lda + k0 + q * 4);
            As[(q * 4 + 0) * 132 + r] = v.x;
            As[(q * 4 + 1) * 132 + r] = v.y;
            As[(q * 4 + 2) * 132 + r] = v.z;
            As[(q * 4 + 3) * 132 + r] = v.w;
        }
        // W tile: 64x16, 1 float4 per thread, store transposed [k][n]
        {
            int r = tid >> 2, q = tid & 3;
            float4 v = *(const float4*)(Wb + (size_t)r * ldw + k0 + q * 4);
            Bs[(q * 4 + 0) * 68 + r] = v.x;
            Bs[(q * 4 + 1) * 68 + r] = v.y;
            Bs[(q * 4 + 2) * 68 + r] = v.z;
            Bs[(q * 4 + 3) * 68 + r] = v.w;
        }
        __syncthreads();
#pragma unroll
        for (int k = 0; k < 16; k++) {
            float4 a0 = *(const float4*)(As + k * 132 + ty * 8);
            float4 a1 = *(const float4*)(As + k * 132 + ty * 8 + 4);
            float4 b0 = *(const float4*)(Bs + k * 68 + tx * 4);
            float a[8] = {a0.x, a0.y, a0.z, a0.w, a1.x, a1.y, a1.z, a1.w};
            float bb[4] = {b0.x, b0.y, b0.z, b0.w};
#pragma unroll
            for (int i = 0; i < 8; i++)
#pragma unroll
                for (int j = 0; j < 4; j++) acc[i][j] = fmaf(a[i], bb[j], acc[i][j]);
        }
        __syncthreads();
    }

    // epilogue: float4 stores
#pragma unroll
    for (int i = 0; i < 8; i++) {
        int row = bm + ty * 8 + i;
        int col = bn + tx * 4;
        float4 v;
        v.x = acc[i][0]; v.y = acc[i][1]; v.z = acc[i][2]; v.w = acc[i][3];
        if (ACT == 1) {
            v.x = softplusf(v.x + bias[col + 0]);
            v.y = softplusf(v.y + bias[col + 1]);
            v.z = softplusf(v.z + bias[col + 2]);
            v.w = softplusf(v.w + bias[col + 3]);
        }
        *(float4*)(C + (size_t)row * ldc + col) = v;
    }
}

// ---------------- depthwise causal conv (k=4) + bias + SiLU -------------------
__global__ void conv_silu_kernel(const float* __restrict__ xz, const float* __restrict__ w,
                                 const float* __restrict__ b, float* __restrict__ out) {
    int idx = blockIdx.x * 256 + threadIdx.x;
    if (idx >= ML * DI) return;
    int d = idx & (DI - 1);
    int bl = idx >> 10;               // b*L + l
    int l = bl & (LL - 1);
    float acc = b[d];
#pragma unroll
    for (int k = 0; k < 4; k++) {
        int lk = l - 3 + k;
        if (lk >= 0) acc = fmaf(w[d * 4 + k], xz[(size_t)(bl - 3 + k) * (2 * DI) + d], acc);
    }
    out[idx] = siluf(acc);
}

// ---------------- selective scan: 16 lanes per (b,d) channel ------------------
__global__ void scan_kernel(const float* __restrict__ dtb, const float* __restrict__ ub,
                            const float* __restrict__ xdbl, const float* __restrict__ A_log,
                            float* __restrict__ ys) {
    int grp = threadIdx.x >> 4;       // 16 channels per 256-thread block
    int n = threadIdx.x & 15;         // state index
    int ch = blockIdx.x * 16 + grp;   // 0..4095
    int b = ch >> 10;
    int d = ch & (DI - 1);

    float An = -__expf(A_log[d * DS + n]);

    const float* dtp = dtb + (size_t)b * LL * DI + d;
    const float* up  = ub  + (size_t)b * LL * DI + d;
    const float* bp  = xdbl + (size_t)b * LL * 64 + DTR + n;   // B at col 32+n, C at 48+n
    float* yp = ys + (size_t)b * LL * DI + d;

    float h = 0.f;
    for (int t = 0; t < LL; t++) {
        float dt = __ldg(dtp + (size_t)t * DI);
        float u  = __ldg(up  + (size_t)t * DI);
        float Bn = __ldg(bp + (size_t)t * 64);
        float Cn = __ldg(bp + (size_t)t * 64 + DS);
        float dA = fexp(dt * An);
        h = fmaf(dA, h, dt * u * Bn);
        float p = h * Cn;
        p += __shfl_xor_sync(0xffffffffu, p, 8, 16);
        p += __shfl_xor_sync(0xffffffffu, p, 4, 16);
        p += __shfl_xor_sync(0xffffffffu, p, 2, 16);
        p += __shfl_xor_sync(0xffffffffu, p, 1, 16);
        if (n == 0) yp[(size_t)t * DI] = p;
    }
}

// ---------------- y = (y_scan + u*D) * silu(z)  (in place into g_ys) ---------
__global__ void gate_kernel(float* __restrict__ ys, const float* __restrict__ u,
                            const float* __restrict__ xz, const float* __restrict__ Dskip) {
    int idx = blockIdx.x * 256 + threadIdx.x;
    if (idx >= ML * DI) return;
    int d = idx & (DI - 1);
    size_t bl = (size_t)(idx >> 10);
    float z = xz[bl * (2 * DI) + DI + d];
    float y = fmaf(u[idx], Dskip[d], ys[idx]);
    ys[idx] = y * siluf(z);
}

// ---------------- LayerNorm over 512, in place -------------------------------
__global__ void ln_kernel(float* __restrict__ io, const float* __restrict__ w,
                          const float* __restrict__ b) {
    __shared__ float ssum[4], ssq[4];
    int row = blockIdx.x;
    float* p = io + (size_t)row * DM;
    int t = threadIdx.x;              // 128 threads, 4 floats each
    float4 v = ((float4*)p)[t];
    float s = v.x + v.y + v.z + v.w;
    float q = v.x * v.x + v.y * v.y + v.z * v.z + v.w * v.w;
#pragma unroll
    for (int o = 16; o; o >>= 1) {
        s += __shfl_xor_sync(0xffffffffu, s, o);
        q += __shfl_xor_sync(0xffffffffu, q, o);
    }
    if ((t & 31) == 0) { ssum[t >> 5] = s; ssq[t >> 5] = q; }
    __syncthreads();
    s = ssum[0] + ssum[1] + ssum[2] + ssum[3];
    q = ssq[0] + ssq[1] + ssq[2] + ssq[3];
    float mu = s * (1.f / DM);
    float var = q * (1.f / DM) - mu * mu;
    float inv = rsqrtf(var + 1e-5f);
    int c = t * 4;
    float4 o;
    o.x = (v.x - mu) * inv * w[c + 0] + b[c + 0];
    o.y = (v.y - mu) * inv * w[c + 1] + b[c + 1];
    o.z = (v.z - mu) * inv * w[c + 2] + b[c + 2];
    o.w = (v.w - mu) * inv * w[c + 3] + b[c + 3];
    ((float4*)p)[t] = o;
}

// ---------------- launch ------------------------------------------------------
extern "C" void kernel_launch(void* const* d_in, const int* in_sizes, int n_in,
                              void* d_out, int out_size) {
    const float* x_in      = (const float*)d_in[0];   // [4,2048,512]
    const float* in_proj_w = (const float*)d_in[1];   // [2048,512]
    const float* conv_w    = (const float*)d_in[2];   // [1024,1,4]
    const float* conv_b    = (const float*)d_in[3];   // [1024]
    const float* x_proj_w  = (const float*)d_in[4];   // [64,1024]
    const float* dt_proj_w = (const float*)d_in[5];   // [1024,32]
    const float* dt_proj_b = (const float*)d_in[6];   // [1024]
    const float* A_log     = (const float*)d_in[7];   // [1024,16]
    const float* D_skip    = (const float*)d_in[8];   // [1024]
    const float* out_proj_w= (const float*)d_in[9];   // [512,1024]
    const float* ln_w      = (const float*)d_in[10];  // [512]
    const float* ln_b      = (const float*)d_in[11];  // [512]
    float* out = (float*)d_out;

    static float *p_xz = nullptr, *p_xc = nullptr, *p_xdbl = nullptr, *p_dt = nullptr, *p_ys = nullptr;
    if (!p_xz) {
        cudaGetSymbolAddress((void**)&p_xz, g_xz);
        cudaGetSymbolAddress((void**)&p_xc, g_xc);
        cudaGetSymbolAddress((void**)&p_xdbl, g_xdbl);
        cudaGetSymbolAddress((void**)&p_dt, g_dt);
        cudaGetSymbolAddress((void**)&p_ys, g_ys);
    }

    // 1) xz = X @ in_proj_w^T   [8192,2048]
    sgemm_kernel<0><<<dim3(2 * DI / 64, ML / 128), 256>>>(
        x_in, in_proj_w, nullptr, p_xz, DM, DM, DM, 2 * DI);

    // 2) u = silu(depthwise_conv(x) + b)   [8192,1024]
    conv_silu_kernel<<<(ML * DI) / 256, 256>>>(p_xz, conv_w, conv_b, p_xc);

    // 3) x_dbl = u @ x_proj_w^T   [8192,64]
    sgemm_kernel<0><<<dim3(64 / 64, ML / 128), 256>>>(
        p_xc, x_proj_w, nullptr, p_xdbl, DI, DI, DI, 64);

    // 4) dt = softplus(x_dbl[:, :32] @ dt_proj_w^T + b)   [8192,1024]
    sgemm_kernel<1><<<dim3(DI / 64, ML / 128), 256>>>(
        p_xdbl, dt_proj_w, dt_proj_b, p_dt, DTR, 64, DTR, DI);

    // 5) selective scan -> y_scan   [8192,1024]
    scan_kernel<<<BB * DI / 16, 256>>>(p_dt, p_xc, p_xdbl, A_log, p_ys);

    // 6) y = (y_scan + u*D) * silu(z)
    gate_kernel<<<(ML * DI) / 256, 256>>>(p_ys, p_xc, p_xz, D_skip);

    // 7) out = y @ out_proj_w^T   [8192,512]
    sgemm_kernel<0><<<dim3(DM / 64, ML / 128), 256>>>(
        p_ys, out_proj_w, nullptr, out, DI, DI, DI, DM);

    // 8) LayerNorm in place
    ln_kernel<<<ML, 128>>>(out, ln_w, ln_b);
}

// round 3
// speedup vs baseline: 1.3307x; 1.3307x over previous
#include <cuda_runtime.h>
#include <cuda_bf16.h>
#include <cstdint>
#include <cstddef>

// Problem constants
#define BB 4
#define LL 2048
#define DM 512
#define DI 1024            // D_INNER
#define DS 16              // D_STATE
#define DTR 32             // DT_RANK
#define ML (BB*LL)         // 8192 rows

// ---------------- scratch (no allocations allowed) ----------------
__device__ float g_xz  [(size_t)ML * 2 * DI];
__device__ float g_xc  [(size_t)ML * DI];
__device__ float g_xdbl[(size_t)ML * 64];
__device__ float g_dt  [(size_t)ML * DI];
__device__ float g_ys  [(size_t)ML * DI];

// bf16 split buffers (16B-aligned for cp.async)
__device__ __align__(256) __nv_bfloat16 g_xhi [(size_t)ML * DM];
__device__ __align__(256) __nv_bfloat16 g_xlo [(size_t)ML * DM];
__device__ __align__(256) __nv_bfloat16 g_w1hi[(size_t)2 * DI * DM];
__device__ __align__(256) __nv_bfloat16 g_w1lo[(size_t)2 * DI * DM];
__device__ __align__(256) __nv_bfloat16 g_yhi [(size_t)ML * DI];
__device__ __align__(256) __nv_bfloat16 g_ylo [(size_t)ML * DI];
__device__ __align__(256) __nv_bfloat16 g_w2hi[(size_t)DM * DI];
__device__ __align__(256) __nv_bfloat16 g_w2lo[(size_t)DM * DI];

// ---------------- PTX helpers (base ISA only) ----------------
__device__ __forceinline__ uint32_t smem_u32(const void* p) {
    uint32_t a;
    asm("{ .reg .u64 t; cvta.to.shared.u64 t, %1; cvt.u32.u64 %0, t; }" : "=r"(a) : "l"(p));
    return a;
}
__device__ __forceinline__ void cp_async16(uint32_t saddr, const void* gaddr) {
    asm volatile("cp.async.cg.shared.global [%0], [%1], 16;" :: "r"(saddr), "l"(gaddr));
}
__device__ __forceinline__ void ldm_x4(uint32_t* r, uint32_t addr) {
    asm volatile("ldmatrix.sync.aligned.m8n8.x4.shared.b16 {%0,%1,%2,%3}, [%4];"
                 : "=r"(r[0]), "=r"(r[1]), "=r"(r[2]), "=r"(r[3]) : "r"(addr));
}
__device__ __forceinline__ void ldm_x2(uint32_t* r, uint32_t addr) {
    asm volatile("ldmatrix.sync.aligned.m8n8.x2.shared.b16 {%0,%1}, [%2];"
                 : "=r"(r[0]), "=r"(r[1]) : "r"(addr));
}
__device__ __forceinline__ void mma_bf16(float* d, const uint32_t* a, const uint32_t* b) {
    asm volatile(
        "mma.sync.aligned.m16n8k16.row.col.f32.bf16.bf16.f32 "
        "{%0,%1,%2,%3}, {%4,%5,%6,%7}, {%8,%9}, {%0,%1,%2,%3};"
        : "+f"(d[0]), "+f"(d[1]), "+f"(d[2]), "+f"(d[3])
        : "r"(a[0]), "r"(a[1]), "r"(a[2]), "r"(a[3]), "r"(b[0]), "r"(b[1]));
}

// ---------------- math helpers ----------------
__device__ __forceinline__ float fexp(float x) {
    float y = x * 1.4426950408889634f;
    y = fmaxf(y, -126.0f);
    float r = rintf(y);
    float f = y - r;
    float p = 0.0013333558f;
    p = fmaf(p, f, 0.0096181298f);
    p = fmaf(p, f, 0.0555041087f);
    p = fmaf(p, f, 0.2402265070f);
    p = fmaf(p, f, 0.6931471806f);
    p = fmaf(p, f, 1.0f);
    int e = (int)r;
    return __int_as_float(__float_as_int(p) + (e << 23));
}
__device__ __forceinline__ float softplusf(float x) {
    return (x > 20.f) ? x : log1pf(__expf(x));
}
__device__ __forceinline__ float siluf(float x) {
    return x / (1.f + __expf(-x));
}

// ---------------- fp32 -> bf16 hi/lo split -------------------------
__global__ void cvt_split_kernel(const float* __restrict__ x, __nv_bfloat16* __restrict__ hi,
                                 __nv_bfloat16* __restrict__ lo, int n4) {
    int i = blockIdx.x * 256 + threadIdx.x;
    if (i >= n4) return;
    float4 v = ((const float4*)x)[i];
    __nv_bfloat16 h0 = __float2bfloat16(v.x);
    __nv_bfloat16 h1 = __float2bfloat16(v.y);
    __nv_bfloat16 h2 = __float2bfloat16(v.z);
    __nv_bfloat16 h3 = __float2bfloat16(v.w);
    __nv_bfloat16 l0 = __float2bfloat16(v.x - __bfloat162float(h0));
    __nv_bfloat16 l1 = __float2bfloat16(v.y - __bfloat162float(h1));
    __nv_bfloat16 l2 = __float2bfloat16(v.z - __bfloat162float(h2));
    __nv_bfloat16 l3 = __float2bfloat16(v.w - __bfloat162float(h3));
    __nv_bfloat162 hp0; hp0.x = h0; hp0.y = h1;
    __nv_bfloat162 hp1; hp1.x = h2; hp1.y = h3;
    __nv_bfloat162 lp0; lp0.x = l0; lp0.y = l1;
    __nv_bfloat162 lp1; lp1.x = l2; lp1.y = l3;
    ((__nv_bfloat162*)hi)[i * 2 + 0] = hp0;
    ((__nv_bfloat162*)hi)[i * 2 + 1] = hp1;
    ((__nv_bfloat162*)lo)[i * 2 + 0] = lp0;
    ((__nv_bfloat162*)lo)[i * 2 + 1] = lp1;
}

// ---------------- HMMA split-bf16 GEMM -----------------------------
// C[m,n] = sum_k A[m,k]*W[n,k]; A,W pre-split into bf16 hi/lo.
// CTA tile 128x128, BK=32, double-buffered cp.async, 8 warps (2x4).
#define GPITCH 40                      // smem row pitch in bf16 (32 + 8 pad)
#define GTILE  (128 * GPITCH * 2)      // 10240 B per tile
#define GSTAGE (4 * GTILE)             // 40960 B per stage (Ahi,Alo,Bhi,Blo)
#define GSMEM  (2 * GSTAGE)            // 81920 B

__global__ __launch_bounds__(256) void mma_gemm_kernel(
    const __nv_bfloat16* __restrict__ Ahi, const __nv_bfloat16* __restrict__ Alo,
    const __nv_bfloat16* __restrict__ Bhi, const __nv_bfloat16* __restrict__ Blo,
    float* __restrict__ C, int K, int ldc) {
    extern __shared__ __align__(128) char smem[];
    const int tid = threadIdx.x;
    const int lane = tid & 31;
    const int wid = tid >> 5;
    const int warp_m = wid >> 2;      // 0..1  -> 64 rows
    const int warp_n = wid & 3;       // 0..3  -> 32 cols
    const int bm = blockIdx.y * 128;
    const int bn = blockIdx.x * 128;

    uint32_t sb = smem_u32(smem);
    const __nv_bfloat16* gbase[4] = {
        Ahi + (size_t)bm * K, Alo + (size_t)bm * K,
        Bhi + (size_t)bn * K, Blo + (size_t)bn * K };

    float acc[4][4][4];
#pragma unroll
    for (int i = 0; i < 4; i++)
#pragma unroll
        for (int j = 0; j < 4; j++)
#pragma unroll
            for (int v = 0; v < 4; v++) acc[i][j][v] = 0.f;

    const int nch = K >> 5;

    // prefetch chunk 0 into stage 0
    {
#pragma unroll
        for (int i = 0; i < 8; i++) {
            int seg = tid + i * 256;            // 2048 segs: 4 tiles x 128 rows x 4
            int tile = seg >> 9;
            int r = (seg >> 2) & 127;
            int q = seg & 3;
            cp_async16(sb + tile * GTILE + (r * GPITCH + q * 8) * 2,
                       gbase[tile] + (size_t)r * K + q * 8);
        }
        asm volatile("cp.async.commit_group;");
    }

    // ldmatrix base addresses (per-thread)
    const int arow = warp_m * 64 + (lane & 15);
    const int acol = (lane >> 4) * 8;
    const int brow = warp_n * 32 + (lane & 7);
    const int bcol = ((lane >> 3) & 1) * 8;

    for (int c = 0; c < nch; c++) {
        const int s = c & 1;
        if (c + 1 < nch) {
            const int k0 = (c + 1) << 5;
            const int s1 = (c + 1) & 1;
#pragma unroll
            for (int i = 0; i < 8; i++) {
                int seg = tid + i * 256;
                int tile = seg >> 9;
                int r = (seg >> 2) & 127;
                int q = seg & 3;
                cp_async16(sb + s1 * GSTAGE + tile * GTILE + (r * GPITCH + q * 8) * 2,
                           gbase[tile] + (size_t)r * K + k0 + q * 8);
            }
            asm volatile("cp.async.commit_group;");
            asm volatile("cp.async.wait_group 1;" ::: "memory");
        } else {
            asm volatile("cp.async.wait_group 0;" ::: "memory");
        }
        __syncthreads();

        uint32_t base = sb + s * GSTAGE;
#pragma unroll
        for (int ks = 0; ks < 2; ks++) {
            uint32_t a_hi[4][4], a_lo[4][4], b_hi[4][2], b_lo[4][2];
#pragma unroll
            for (int im = 0; im < 4; im++) {
                uint32_t off = ((arow + im * 16) * GPITCH + ks * 16 + acol) * 2;
                ldm_x4(a_hi[im], base + 0 * GTILE + off);
                ldm_x4(a_lo[im], base + 1 * GTILE + off);
            }
#pragma unroll
            for (int jn = 0; jn < 4; jn++) {
                uint32_t off = ((brow + jn * 8) * GPITCH + ks * 16 + bcol) * 2;
                ldm_x2(b_hi[jn], base + 2 * GTILE + off);
                ldm_x2(b_lo[jn], base + 3 * GTILE + off);
            }
#pragma unroll
            for (int im = 0; im < 4; im++)
#pragma unroll
                for (int jn = 0; jn < 4; jn++) {
                    mma_bf16(acc[im][jn], a_hi[im], b_hi[jn]);
                    mma_bf16(acc[im][jn], a_hi[im], b_lo[jn]);
                    mma_bf16(acc[im][jn], a_lo[im], b_hi[jn]);
                }
        }
        __syncthreads();
    }

    // epilogue: direct float2 stores
#pragma unroll
    for (int im = 0; im < 4; im++) {
        int r0 = bm + warp_m * 64 + im * 16 + (lane >> 2);
#pragma unroll
        for (int jn = 0; jn < 4; jn++) {
            int col = bn + warp_n * 32 + jn * 8 + (lane & 3) * 2;
            float2 v0; v0.x = acc[im][jn][0]; v0.y = acc[im][jn][1];
            float2 v1; v1.x = acc[im][jn][2]; v1.y = acc[im][jn][3];
            *(float2*)(C + (size_t)r0 * ldc + col) = v0;
            *(float2*)(C + (size_t)(r0 + 8) * ldc + col) = v1;
        }
    }
}

// ---------------- SIMT SGEMM (small GEMMs) -------------------------
template <int ACT>
__global__ void sgemm_kernel(const float* __restrict__ A, const float* __restrict__ W,
                             const float* __restrict__ bias, float* __restrict__ C,
                             int K, int lda, int ldw, int ldc) {
    __shared__ float As[16 * 132];
    __shared__ float Bs[16 * 68];
    const int tid = threadIdx.x;
    const int tx = tid & 15;
    const int ty = tid >> 4;
    const int bm = blockIdx.y * 128;
    const int bn = blockIdx.x * 64;

    const float* Ab = A + (size_t)bm * lda;
    const float* Wb = W + (size_t)bn * ldw;

    float acc[8][4];
#pragma unroll
    for (int i = 0; i < 8; i++)
#pragma unroll
        for (int j = 0; j < 4; j++) acc[i][j] = 0.f;

    for (int k0 = 0; k0 < K; k0 += 16) {
#pragma unroll
        for (int i = 0; i < 2; i++) {
            int qid = tid + i * 256;
            int r = qid >> 2, q = qid & 3;
            float4 v = *(const float4*)(Ab + (size_t)r * lda + k0 + q * 4);
            As[(q * 4 + 0) * 132 + r] = v.x;
            As[(q * 4 + 1) * 132 + r] = v.y;
            As[(q * 4 + 2) * 132 + r] = v.z;
            As[(q * 4 + 3) * 132 + r] = v.w;
        }
        {
            int r = tid >> 2, q = tid & 3;
            float4 v = *(const float4*)(Wb + (size_t)r * ldw + k0 + q * 4);
            Bs[(q * 4 + 0) * 68 + r] = v.x;
            Bs[(q * 4 + 1) * 68 + r] = v.y;
            Bs[(q * 4 + 2) * 68 + r] = v.z;
            Bs[(q * 4 + 3) * 68 + r] = v.w;
        }
        __syncthreads();
#pragma unroll
        for (int k = 0; k < 16; k++) {
            float4 a0 = *(const float4*)(As + k * 132 + ty * 8);
            float4 a1 = *(const float4*)(As + k * 132 + ty * 8 + 4);
            float4 b0 = *(const float4*)(Bs + k * 68 + tx * 4);
            float a[8] = {a0.x, a0.y, a0.z, a0.w, a1.x, a1.y, a1.z, a1.w};
            float bb[4] = {b0.x, b0.y, b0.z, b0.w};
#pragma unroll
            for (int i = 0; i < 8; i++)
#pragma unroll
                for (int j = 0; j < 4; j++) acc[i][j] = fmaf(a[i], bb[j], acc[i][j]);
        }
        __syncthreads();
    }

#pragma unroll
    for (int i = 0; i < 8; i++) {
        int row = bm + ty * 8 + i;
        int col = bn + tx * 4;
        float4 v;
        v.x = acc[i][0]; v.y = acc[i][1]; v.z = acc[i][2]; v.w = acc[i][3];
        if (ACT == 1) {
            v.x = softplusf(v.x + bias[col + 0]);
            v.y = softplusf(v.y + bias[col + 1]);
            v.z = softplusf(v.z + bias[col + 2]);
            v.w = softplusf(v.w + bias[col + 3]);
        }
        *(float4*)(C + (size_t)row * ldc + col) = v;
    }
}

// ---------------- depthwise causal conv (k=4) + bias + SiLU --------
__global__ void conv_silu_kernel(const float* __restrict__ xz, const float* __restrict__ w,
                                 const float* __restrict__ b, float* __restrict__ out) {
    int idx = blockIdx.x * 256 + threadIdx.x;
    if (idx >= ML * DI) return;
    int d = idx & (DI - 1);
    int bl = idx >> 10;
    int l = bl & (LL - 1);
    float acc = b[d];
#pragma unroll
    for (int k = 0; k < 4; k++) {
        int lk = l - 3 + k;
        if (lk >= 0) acc = fmaf(w[d * 4 + k], xz[(size_t)(bl - 3 + k) * (2 * DI) + d], acc);
    }
    out[idx] = siluf(acc);
}

// ---------------- selective scan ----------------------------------
__global__ void scan_kernel(const float* __restrict__ dtb, const float* __restrict__ ub,
                            const float* __restrict__ xdbl, const float* __restrict__ A_log,
                            float* __restrict__ ys) {
    int grp = threadIdx.x >> 4;
    int n = threadIdx.x & 15;
    int ch = blockIdx.x * 16 + grp;
    int b = ch >> 10;
    int d = ch & (DI - 1);

    float An = -__expf(A_log[d * DS + n]);

    const float* dtp = dtb + (size_t)b * LL * DI + d;
    const float* up  = ub  + (size_t)b * LL * DI + d;
    const float* bp  = xdbl + (size_t)b * LL * 64 + DTR + n;
    float* yp = ys + (size_t)b * LL * DI + d;

    float h = 0.f;
    for (int t = 0; t < LL; t++) {
        float dt = __ldg(dtp + (size_t)t * DI);
        float u  = __ldg(up  + (size_t)t * DI);
        float Bn = __ldg(bp + (size_t)t * 64);
        float Cn = __ldg(bp + (size_t)t * 64 + DS);
        float dA = fexp(dt * An);
        h = fmaf(dA, h, dt * u * Bn);
        float p = h * Cn;
        p += __shfl_xor_sync(0xffffffffu, p, 8, 16);
        p += __shfl_xor_sync(0xffffffffu, p, 4, 16);
        p += __shfl_xor_sync(0xffffffffu, p, 2, 16);
        p += __shfl_xor_sync(0xffffffffu, p, 1, 16);
        if (n == 0) yp[(size_t)t * DI] = p;
    }
}

// ---------------- gate --------------------------------------------
__global__ void gate_kernel(float* __restrict__ ys, const float* __restrict__ u,
                            const float* __restrict__ xz, const float* __restrict__ Dskip) {
    int idx = blockIdx.x * 256 + threadIdx.x;
    if (idx >= ML * DI) return;
    int d = idx & (DI - 1);
    size_t bl = (size_t)(idx >> 10);
    float z = xz[bl * (2 * DI) + DI + d];
    float y = fmaf(u[idx], Dskip[d], ys[idx]);
    ys[idx] = y * siluf(z);
}

// ---------------- LayerNorm ---------------------------------------
__global__ void ln_kernel(float* __restrict__ io, const float* __restrict__ w,
                          const float* __restrict__ b) {
    __shared__ float ssum[4], ssq[4];
    int row = blockIdx.x;
    float* p = io + (size_t)row * DM;
    int t = threadIdx.x;
    float4 v = ((float4*)p)[t];
    float s = v.x + v.y + v.z + v.w;
    float q = v.x * v.x + v.y * v.y + v.z * v.z + v.w * v.w;
#pragma unroll
    for (int o = 16; o; o >>= 1) {
        s += __shfl_xor_sync(0xffffffffu, s, o);
        q += __shfl_xor_sync(0xffffffffu, q, o);
    }
    if ((t & 31) == 0) { ssum[t >> 5] = s; ssq[t >> 5] = q; }
    __syncthreads();
    s = ssum[0] + ssum[1] + ssum[2] + ssum[3];
    q = ssq[0] + ssq[1] + ssq[2] + ssq[3];
    float mu = s * (1.f / DM);
    float var = q * (1.f / DM) - mu * mu;
    float inv = rsqrtf(var + 1e-5f);
    int c = t * 4;
    float4 o;
    o.x = (v.x - mu) * inv * w[c + 0] + b[c + 0];
    o.y = (v.y - mu) * inv * w[c + 1] + b[c + 1];
    o.z = (v.z - mu) * inv * w[c + 2] + b[c + 2];
    o.w = (v.w - mu) * inv * w[c + 3] + b[c + 3];
    ((float4*)p)[t] = o;
}

// ---------------- launch ------------------------------------------
extern "C" void kernel_launch(void* const* d_in, const int* in_sizes, int n_in,
                              void* d_out, int out_size) {
    const float* x_in      = (const float*)d_in[0];
    const float* in_proj_w = (const float*)d_in[1];
    const float* conv_w    = (const float*)d_in[2];
    const float* conv_b    = (const float*)d_in[3];
    const float* x_proj_w  = (const float*)d_in[4];
    const float* dt_proj_w = (const float*)d_in[5];
    const float* dt_proj_b = (const float*)d_in[6];
    const float* A_log     = (const float*)d_in[7];
    const float* D_skip    = (const float*)d_in[8];
    const float* out_proj_w= (const float*)d_in[9];
    const float* ln_w      = (const float*)d_in[10];
    const float* ln_b      = (const float*)d_in[11];
    float* out = (float*)d_out;

    static float *p_xz=nullptr,*p_xc=nullptr,*p_xdbl=nullptr,*p_dt=nullptr,*p_ys=nullptr;
    static __nv_bfloat16 *p_xhi,*p_xlo,*p_w1hi,*p_w1lo,*p_yhi,*p_ylo,*p_w2hi,*p_w2lo;
    if (!p_xz) {
        cudaGetSymbolAddress((void**)&p_xz, g_xz);
        cudaGetSymbolAddress((void**)&p_xc, g_xc);
        cudaGetSymbolAddress((void**)&p_xdbl, g_xdbl);
        cudaGetSymbolAddress((void**)&p_dt, g_dt);
        cudaGetSymbolAddress((void**)&p_ys, g_ys);
        cudaGetSymbolAddress((void**)&p_xhi, g_xhi);
        cudaGetSymbolAddress((void**)&p_xlo, g_xlo);
        cudaGetSymbolAddress((void**)&p_w1hi, g_w1hi);
        cudaGetSymbolAddress((void**)&p_w1lo, g_w1lo);
        cudaGetSymbolAddress((void**)&p_yhi, g_yhi);
        cudaGetSymbolAddress((void**)&p_ylo, g_ylo);
        cudaGetSymbolAddress((void**)&p_w2hi, g_w2hi);
        cudaGetSymbolAddress((void**)&p_w2lo, g_w2lo);
        cudaFuncSetAttribute(mma_gemm_kernel, cudaFuncAttributeMaxDynamicSharedMemorySize, GSMEM);
    }

    // 0) splits for GEMM1
    cvt_split_kernel<<<(ML * DM / 4) / 256, 256>>>(x_in, p_xhi, p_xlo, ML * DM / 4);
    cvt_split_kernel<<<(2 * DI * DM / 4) / 256, 256>>>(in_proj_w, p_w1hi, p_w1lo, 2 * DI * DM / 4);

    // 1) xz = X @ in_proj_w^T   [8192,2048]  (HMMA tensor cores)
    mma_gemm_kernel<<<dim3(2 * DI / 128, ML / 128), 256, GSMEM>>>(
        p_xhi, p_xlo, p_w1hi, p_w1lo, p_xz, DM, 2 * DI);

    // 2) u = silu(conv(x)+b)
    conv_silu_kernel<<<(ML * DI) / 256, 256>>>(p_xz, conv_w, conv_b, p_xc);

    // 3) x_dbl = u @ x_proj_w^T   [8192,64]
    sgemm_kernel<0><<<dim3(1, ML / 128), 256>>>(p_xc, x_proj_w, nullptr, p_xdbl, DI, DI, DI, 64);

    // 4) dt = softplus(x_dbl[:, :32] @ dt_proj_w^T + b)
    sgemm_kernel<1><<<dim3(DI / 64, ML / 128), 256>>>(p_xdbl, dt_proj_w, dt_proj_b, p_dt, DTR, 64, DTR, DI);

    // 5) selective scan
    scan_kernel<<<BB * DI / 16, 256>>>(p_dt, p_xc, p_xdbl, A_log, p_ys);

    // 6) gate
    gate_kernel<<<(ML * DI) / 256, 256>>>(p_ys, p_xc, p_xz, D_skip);

    // 7) splits + out = y @ out_proj_w^T  (HMMA tensor cores)
    cvt_split_kernel<<<(ML * DI / 4) / 256, 256>>>(p_ys, p_yhi, p_ylo, ML * DI / 4);
    cvt_split_kernel<<<(DM * DI / 4) / 256, 256>>>(out_proj_w, p_w2hi, p_w2lo, DM * DI / 4);
    mma_gemm_kernel<<<dim3(DM / 128, ML / 128), 256, GSMEM>>>(
        p_yhi, p_ylo, p_w2hi, p_w2lo, out, DI, DM);

    // 8) LayerNorm in place
    ln_kernel<<<ML, 128>>>(out, ln_w, ln_b);
}